// round 1
// baseline (speedup 1.0000x reference)
#include <cuda_runtime.h>
#include <math.h>

#define DIM   256
#define NH    8
#define HD    32
#define NTOK  98
#define BW    2048
#define TBL   507                 // (2*2-1)*(2*7-1)*(2*7-1)
#define M_TOT (BW*NTOK)           // 200704
#define QST   33                  // padded smem row stride for q/k/v

// ---------------- device scratch (no allocations allowed) ----------------
__device__ float g_qkv[(size_t)BW * NTOK * 3 * DIM];   // 616 MB
__device__ float g_att[(size_t)BW * NTOK * DIM];       // 205 MB
__device__ float g_qkvwT[DIM * 3 * DIM];               // [K=256][N=768]
__device__ float g_projwT[DIM * DIM];                  // [K=256][N=256]
__device__ float g_bt[TBL * NH];                       // 16*sigmoid(cpb) table
__device__ float g_bias768[3 * DIM];
__device__ float g_scale[NH];

// ---------------- setup: fused bias + per-head logit scale ----------------
__global__ void setup_small(const float* __restrict__ qb,
                            const float* __restrict__ vb,
                            const float* __restrict__ ls) {
    int t = threadIdx.x;                       // 768 threads
    float b;
    if (t < 256)       b = qb[t];
    else if (t < 512)  b = 0.f;
    else               b = vb[t - 512];
    g_bias768[t] = b;
    if (t < NH) g_scale[t] = expf(fminf(ls[t], 4.6051701860f)); // log(100)
}

// ---------------- weight transpose: dst[k*N+n] = src[n*K+k] ----------------
__global__ void transpose_k(const float* __restrict__ src, float* __restrict__ dst,
                            int N, int K) {
    int i = blockIdx.x * 256 + threadIdx.x;
    if (i < N * K) {
        int n = i / K, k = i % K;
        dst[k * N + n] = src[i];
    }
}

// ---------------- CPB MLP: table -> relu -> w2 -> 16*sigmoid ----------------
__global__ void cpb_kernel(const float* __restrict__ w1, const float* __restrict__ b1,
                           const float* __restrict__ w2) {
    __shared__ float hid[512];
    int t = blockIdx.x;                        // 0..506
    int a = t / 169, rem = t % 169, b = rem / 13, c = rem % 13;
    const float eps = 1e-6f;
    float ga = (float)(a - 1) / (2.f - (1.f - eps)) * 8.f;
    float gb = (float)(b - 6) / (7.f - (1.f - eps)) * 8.f;
    float gc = (float)(c - 6) / (7.f - (1.f - eps)) * 8.f;
    const float il8 = 1.f / log2f(8.f);
    ga = copysignf(log2f(fabsf(ga) + 1.f) * il8, ga);
    gb = copysignf(log2f(fabsf(gb) + 1.f) * il8, gb);
    gc = copysignf(log2f(fabsf(gc) + 1.f) * il8, gc);
    int j = threadIdx.x;                       // 512 threads
    float hv = ga * w1[j * 3 + 0] + gb * w1[j * 3 + 1] + gc * w1[j * 3 + 2] + b1[j];
    hid[j] = fmaxf(hv, 0.f);
    __syncthreads();
    if (j < NH) {
        float acc = 0.f;
        for (int q = 0; q < 512; q++) acc += hid[q] * w2[j * 512 + q];
        g_bt[t * NH + j] = 16.f / (1.f + expf(-acc));
    }
}

// ---------------- 128x128x8 SGEMM, C = A @ BT + bias ----------------
// A: [M,256] row-major (K contiguous); BT: [256,N] (N contiguous); K fixed = 256.
__global__ __launch_bounds__(256) void sgemm128(const float* __restrict__ A,
                                                const float* __restrict__ BT,
                                                const float* __restrict__ bias,
                                                float* __restrict__ C, int N) {
    __shared__ float As[8][132];
    __shared__ float Bs[8][132];
    int tid  = threadIdx.x;
    int m0   = blockIdx.y * 128, n0 = blockIdx.x * 128;
    int trow = tid >> 4, tcol = tid & 15;
    int ar   = tid >> 1, ac4  = (tid & 1) * 4;
    int br   = tid >> 5, bc4  = (tid & 31) * 4;
    float acc[8][8] = {};
    const float* Ap = A  + (size_t)(m0 + ar) * 256 + ac4;
    const float* Bp = BT + (size_t)br * N + n0 + bc4;
    for (int k0 = 0; k0 < 256; k0 += 8) {
        float4 av = *(const float4*)(Ap + k0);
        float4 bv = *(const float4*)(Bp + (size_t)k0 * N);
        As[ac4 + 0][ar] = av.x; As[ac4 + 1][ar] = av.y;
        As[ac4 + 2][ar] = av.z; As[ac4 + 3][ar] = av.w;
        *(float4*)&Bs[br][bc4] = bv;
        __syncthreads();
        #pragma unroll
        for (int kk = 0; kk < 8; kk++) {
            float4 a0 = *(const float4*)&As[kk][trow * 8];
            float4 a1 = *(const float4*)&As[kk][trow * 8 + 4];
            float4 b0 = *(const float4*)&Bs[kk][tcol * 8];
            float4 b1 = *(const float4*)&Bs[kk][tcol * 8 + 4];
            float a[8] = {a0.x, a0.y, a0.z, a0.w, a1.x, a1.y, a1.z, a1.w};
            float b[8] = {b0.x, b0.y, b0.z, b0.w, b1.x, b1.y, b1.z, b1.w};
            #pragma unroll
            for (int i = 0; i < 8; i++)
                #pragma unroll
                for (int j = 0; j < 8; j++) acc[i][j] += a[i] * b[j];
        }
        __syncthreads();
    }
    #pragma unroll
    for (int i = 0; i < 8; i++) {
        float* cp = C + (size_t)(m0 + trow * 8 + i) * N + n0 + tcol * 8;
        #pragma unroll
        for (int j = 0; j < 8; j++) cp[j] = acc[i][j] + bias[n0 + tcol * 8 + j];
    }
}

// ---------------- fused per-(window,head) attention ----------------
// smem floats: 3*98*33 + 98*98 + 507 = 19813  (79252 bytes)
#define ATTN_SMEM_FLOATS (3 * NTOK * QST + NTOK * NTOK + TBL)

__global__ __launch_bounds__(256, 2) void attn_kernel() {
    extern __shared__ float sm[];
    float* sq  = sm;
    float* sk  = sq + NTOK * QST;
    float* sv  = sk + NTOK * QST;
    float* sS  = sv + NTOK * QST;          // 98*98
    float* sbt = sS + NTOK * NTOK;         // 507
    int bx = blockIdx.x;
    int w = bx >> 3, h = bx & 7;
    int tid = threadIdx.x;

    const float* base = g_qkv + (size_t)w * NTOK * 768 + h * HD;
    for (int e = tid; e < NTOK * HD; e += 256) {
        int n = e >> 5, d = e & 31;
        const float* r = base + (size_t)n * 768;
        sq[n * QST + d] = r[d];
        sk[n * QST + d] = r[256 + d];
        sv[n * QST + d] = r[512 + d];
    }
    for (int e = tid; e < TBL; e += 256) sbt[e] = g_bt[e * NH + h];
    __syncthreads();

    // L2-normalize rows; fold cosine scale into q
    float scale = g_scale[h];
    if (tid < NTOK) {
        float nq = 0.f, nk = 0.f;
        for (int d = 0; d < HD; d++) {
            float a = sq[tid * QST + d]; nq += a * a;
            float b = sk[tid * QST + d]; nk += b * b;
        }
        float iq = scale / fmaxf(sqrtf(nq), 1e-12f);
        float ik = 1.f   / fmaxf(sqrtf(nk), 1e-12f);
        for (int d = 0; d < HD; d++) {
            sq[tid * QST + d] *= iq;
            sk[tid * QST + d] *= ik;
        }
    }
    __syncthreads();

    // S = q @ k^T + rpb  (7x7 register tile, 196 active threads)
    if (tid < 196) {
        int ti = tid / 14, tj = tid % 14;
        float acc[7][7] = {};
        const float* qp = &sq[ti * 7 * QST];
        const float* kp = &sk[tj * 7 * QST];
        for (int d = 0; d < HD; d++) {
            float a[7], b[7];
            #pragma unroll
            for (int i = 0; i < 7; i++) a[i] = qp[i * QST + d];
            #pragma unroll
            for (int j = 0; j < 7; j++) b[j] = kp[j * QST + d];
            #pragma unroll
            for (int i = 0; i < 7; i++)
                #pragma unroll
                for (int j = 0; j < 7; j++) acc[i][j] += a[i] * b[j];
        }
        #pragma unroll
        for (int i = 0; i < 7; i++) {
            int gi = ti * 7 + i;
            int di = gi / 49, ri = gi % 49, hi = ri / 7, wi = ri % 7;
            #pragma unroll
            for (int j = 0; j < 7; j++) {
                int gj = tj * 7 + j;
                int dj = gj / 49, rj = gj % 49, hj = rj / 7, wj = rj % 7;
                int idx = (di - dj + 1) * 169 + (hi - hj + 6) * 13 + (wi - wj + 6);
                sS[gi * NTOK + gj] = acc[i][j] + sbt[idx];
            }
        }
    }
    __syncthreads();

    // row softmax (max-subtracted; logits can reach ~116)
    if (tid < NTOK) {
        float* row = &sS[tid * NTOK];
        float m = -1e30f;
        for (int j = 0; j < NTOK; j++) m = fmaxf(m, row[j]);
        float s = 0.f;
        for (int j = 0; j < NTOK; j++) { float e = __expf(row[j] - m); row[j] = e; s += e; }
        float inv = 1.f / s;
        for (int j = 0; j < NTOK; j++) row[j] *= inv;
    }
    __syncthreads();

    // O = P @ V  (7x4 register tile, 112 active threads), write [b,n,h*32+d]
    if (tid < 112) {
        int ti = tid / 8, tc = tid % 8;
        float acc[7][4] = {};
        for (int j = 0; j < NTOK; j++) {
            float p[7], vv[4];
            #pragma unroll
            for (int i = 0; i < 7; i++) p[i] = sS[(ti * 7 + i) * NTOK + j];
            #pragma unroll
            for (int c = 0; c < 4; c++) vv[c] = sv[j * QST + tc * 4 + c];
            #pragma unroll
            for (int i = 0; i < 7; i++)
                #pragma unroll
                for (int c = 0; c < 4; c++) acc[i][c] += p[i] * vv[c];
        }
        float* outb = g_att + (size_t)w * NTOK * DIM + h * HD + tc * 4;
        #pragma unroll
        for (int i = 0; i < 7; i++)
            #pragma unroll
            for (int c = 0; c < 4; c++)
                outb[(size_t)(ti * 7 + i) * DIM + c] = acc[i][c];
    }
}

// ---------------- launch ----------------
extern "C" void kernel_launch(void* const* d_in, const int* in_sizes, int n_in,
                              void* d_out, int out_size) {
    const float* x      = (const float*)d_in[0];
    const float* qkv_w  = (const float*)d_in[1];
    const float* q_bias = (const float*)d_in[2];
    const float* v_bias = (const float*)d_in[3];
    const float* ls     = (const float*)d_in[4];
    const float* cpb_w1 = (const float*)d_in[5];
    const float* cpb_b1 = (const float*)d_in[6];
    const float* cpb_w2 = (const float*)d_in[7];
    const float* proj_w = (const float*)d_in[8];
    const float* proj_b = (const float*)d_in[9];
    float* out = (float*)d_out;

    float *qkv, *att, *qkvwT, *projwT, *bias768;
    cudaGetSymbolAddress((void**)&qkv,     g_qkv);
    cudaGetSymbolAddress((void**)&att,     g_att);
    cudaGetSymbolAddress((void**)&qkvwT,   g_qkvwT);
    cudaGetSymbolAddress((void**)&projwT,  g_projwT);
    cudaGetSymbolAddress((void**)&bias768, g_bias768);

    setup_small<<<1, 768>>>(q_bias, v_bias, ls);
    transpose_k<<<(768 * 256 + 255) / 256, 256>>>(qkv_w, qkvwT, 768, 256);
    transpose_k<<<(256 * 256 + 255) / 256, 256>>>(proj_w, projwT, 256, 256);
    cpb_kernel<<<TBL, 512>>>(cpb_w1, cpb_b1, cpb_w2);

    // QKV: [200704,256] @ [256,768] + bias768
    sgemm128<<<dim3(3 * DIM / 128, M_TOT / 128), 256>>>(x, qkvwT, bias768, qkv, 3 * DIM);

    int smem_bytes = ATTN_SMEM_FLOATS * (int)sizeof(float);
    cudaFuncSetAttribute(attn_kernel, cudaFuncAttributeMaxDynamicSharedMemorySize, smem_bytes);
    attn_kernel<<<BW * NH, 256, smem_bytes>>>();

    // proj: [200704,256] @ [256,256] + proj_b
    sgemm128<<<dim3(DIM / 128, M_TOT / 128), 256>>>(att, projwT, proj_b, out, DIM);
}

// round 6
// speedup vs baseline: 1.7431x; 1.7431x over previous
#include <cuda_runtime.h>
#include <math.h>
#include <stdint.h>

#define DIM   256
#define NH    8
#define HD    32
#define NTOK  98
#define BW    2048
#define TBL   507                 // (2*2-1)*(2*7-1)*(2*7-1)
#define M_TOT (BW*NTOK)           // 200704
#define QST   33                  // padded smem row stride for q/k/v

// ---------------- device scratch (no allocations allowed) ----------------
__device__ float g_qkv[(size_t)BW * NTOK * 3 * DIM];   // 616 MB
__device__ float g_att[(size_t)BW * NTOK * DIM];       // 205 MB
__device__ float g_qkvwT[DIM * 3 * DIM];               // [K=256][N=768]
__device__ float g_projwT[DIM * DIM];                  // [K=256][N=256]
__device__ float g_bt[TBL * NH];                       // 16*sigmoid(cpb) table
__device__ float g_bias768[3 * DIM];
__device__ float g_scale[NH];

// ---------------- setup: fused bias + per-head logit scale ----------------
__global__ void setup_small(const float* __restrict__ qb,
                            const float* __restrict__ vb,
                            const float* __restrict__ ls) {
    int t = threadIdx.x;                       // 768 threads
    float b;
    if (t < 256)       b = qb[t];
    else if (t < 512)  b = 0.f;
    else               b = vb[t - 512];
    g_bias768[t] = b;
    if (t < NH) g_scale[t] = expf(fminf(ls[t], 4.6051701860f)); // log(100)
}

// ---------------- weight transpose: dst[k*N+n] = src[n*K+k] ----------------
__global__ void transpose_k(const float* __restrict__ src, float* __restrict__ dst,
                            int N, int K) {
    int i = blockIdx.x * 256 + threadIdx.x;
    if (i < N * K) {
        int n = i / K, k = i % K;
        dst[k * N + n] = src[i];
    }
}

// ---------------- CPB MLP: table -> relu -> w2 -> 16*sigmoid ----------------
__global__ void cpb_kernel(const float* __restrict__ w1, const float* __restrict__ b1,
                           const float* __restrict__ w2) {
    __shared__ float hid[512];
    int t = blockIdx.x;                        // 0..506
    int a = t / 169, rem = t % 169, b = rem / 13, c = rem % 13;
    const float eps = 1e-6f;
    float ga = (float)(a - 1) / (2.f - (1.f - eps)) * 8.f;
    float gb = (float)(b - 6) / (7.f - (1.f - eps)) * 8.f;
    float gc = (float)(c - 6) / (7.f - (1.f - eps)) * 8.f;
    const float il8 = 1.f / log2f(8.f);
    ga = copysignf(log2f(fabsf(ga) + 1.f) * il8, ga);
    gb = copysignf(log2f(fabsf(gb) + 1.f) * il8, gb);
    gc = copysignf(log2f(fabsf(gc) + 1.f) * il8, gc);
    int j = threadIdx.x;                       // 512 threads
    float hv = ga * w1[j * 3 + 0] + gb * w1[j * 3 + 1] + gc * w1[j * 3 + 2] + b1[j];
    hid[j] = fmaxf(hv, 0.f);
    __syncthreads();
    if (j < NH) {
        float acc = 0.f;
        for (int q = 0; q < 512; q++) acc += hid[q] * w2[j * 512 + q];
        g_bt[t * NH + j] = 16.f / (1.f + expf(-acc));
    }
}

// ---------------- tf32 helpers ----------------
__device__ __forceinline__ uint32_t f2tf(float x) {
    uint32_t u;
    asm("cvt.rna.tf32.f32 %0, %1;" : "=r"(u) : "f"(x));
    return u;
}

__device__ __forceinline__ void mma_tf32(float* d, const uint32_t* a,
                                         const uint32_t* b, const float* c) {
    asm volatile(
        "mma.sync.aligned.m16n8k8.row.col.f32.tf32.tf32.f32 "
        "{%0,%1,%2,%3}, {%4,%5,%6,%7}, {%8,%9}, {%10,%11,%12,%13};\n"
        : "=f"(d[0]), "=f"(d[1]), "=f"(d[2]), "=f"(d[3])
        : "r"(a[0]), "r"(a[1]), "r"(a[2]), "r"(a[3]),
          "r"(b[0]), "r"(b[1]),
          "f"(c[0]), "f"(c[1]), "f"(c[2]), "f"(c[3]));
}

// ---------------- 128x128 tf32 tensor-core GEMM, C = A @ BT + bias ----------
// A: [M,256] row-major; BT: [256,N] (N contiguous); K fixed = 256.
// PTX ISA m16n8k8 tf32 fragments (g = lane>>2, tg = lane&3):
//   A: a0=(g,tg) a1=(g+8,tg) a2=(g,tg+4) a3=(g+8,tg+4)
//   B: b0=(k=tg,n=g) b1=(k=tg+4,n=g)
//   C: c0,c1=(g, 2tg..2tg+1)  c2,c3=(g+8, 2tg..2tg+1)
__global__ __launch_bounds__(256) void gemm_tf32(const float* __restrict__ A,
                                                 const float* __restrict__ BT,
                                                 const float* __restrict__ bias,
                                                 float* __restrict__ C, int N) {
    __shared__ uint32_t As[128][20];   // [m][k], pad 20
    __shared__ uint32_t Bs[16][132];   // [k][n], pad 132

    int tid = threadIdx.x;
    int m0 = blockIdx.y * 128, n0 = blockIdx.x * 128;
    int wid = tid >> 5, lane = tid & 31;
    int g = lane >> 2, tg = lane & 3;
    int wm = (wid & 3) * 32, wn = (wid >> 2) * 64;

    float acc[2][8][4] = {};

    // gmem staging coords
    int am = tid >> 1, ak = (tid & 1) * 8;           // A: 128 rows x 16 k
    const float* Ap = A + (size_t)(m0 + am) * 256 + ak;
    int bk = tid >> 4, bn = (tid & 15) * 4;          // B: 16 k x 128 n
    const float* Bp = BT + (size_t)bk * N + n0 + bn;

    float4 ra0 = *(const float4*)(Ap);
    float4 ra1 = *(const float4*)(Ap + 4);
    float4 rb0 = *(const float4*)(Bp);
    float4 rb1 = *(const float4*)(Bp + 64);

    for (int k0 = 0; k0 < 256; k0 += 16) {
        // stage current chunk into smem (with tf32 rounding)
        As[am][ak + 0] = f2tf(ra0.x); As[am][ak + 1] = f2tf(ra0.y);
        As[am][ak + 2] = f2tf(ra0.z); As[am][ak + 3] = f2tf(ra0.w);
        As[am][ak + 4] = f2tf(ra1.x); As[am][ak + 5] = f2tf(ra1.y);
        As[am][ak + 6] = f2tf(ra1.z); As[am][ak + 7] = f2tf(ra1.w);
        Bs[bk][bn + 0]  = f2tf(rb0.x); Bs[bk][bn + 1]  = f2tf(rb0.y);
        Bs[bk][bn + 2]  = f2tf(rb0.z); Bs[bk][bn + 3]  = f2tf(rb0.w);
        Bs[bk][bn + 64] = f2tf(rb1.x); Bs[bk][bn + 65] = f2tf(rb1.y);
        Bs[bk][bn + 66] = f2tf(rb1.z); Bs[bk][bn + 67] = f2tf(rb1.w);
        __syncthreads();

        // prefetch next chunk
        if (k0 + 16 < 256) {
            ra0 = *(const float4*)(Ap + k0 + 16);
            ra1 = *(const float4*)(Ap + k0 + 20);
            rb0 = *(const float4*)(Bp + (size_t)(k0 + 16) * N);
            rb1 = *(const float4*)(Bp + (size_t)(k0 + 16) * N + 64);
        }

        #pragma unroll
        for (int kk = 0; kk < 16; kk += 8) {
            uint32_t af[2][4];
            #pragma unroll
            for (int mi = 0; mi < 2; mi++) {
                int r = wm + mi * 16 + g;
                af[mi][0] = As[r    ][kk + tg];
                af[mi][1] = As[r + 8][kk + tg];
                af[mi][2] = As[r    ][kk + tg + 4];
                af[mi][3] = As[r + 8][kk + tg + 4];
            }
            uint32_t bf[8][2];
            #pragma unroll
            for (int ni = 0; ni < 8; ni++) {
                bf[ni][0] = Bs[kk + tg    ][wn + ni * 8 + g];
                bf[ni][1] = Bs[kk + tg + 4][wn + ni * 8 + g];
            }
            #pragma unroll
            for (int mi = 0; mi < 2; mi++)
                #pragma unroll
                for (int ni = 0; ni < 8; ni++)
                    mma_tf32(acc[mi][ni], af[mi], bf[ni], acc[mi][ni]);
        }
        __syncthreads();
    }

    // epilogue: add bias, write
    #pragma unroll
    for (int mi = 0; mi < 2; mi++) {
        #pragma unroll
        for (int ni = 0; ni < 8; ni++) {
            int row = m0 + wm + mi * 16 + g;
            int col = n0 + wn + ni * 8 + 2 * tg;
            float b0v = bias[col], b1v = bias[col + 1];
            *(float2*)&C[(size_t)row * N + col] =
                make_float2(acc[mi][ni][0] + b0v, acc[mi][ni][1] + b1v);
            *(float2*)&C[(size_t)(row + 8) * N + col] =
                make_float2(acc[mi][ni][2] + b0v, acc[mi][ni][3] + b1v);
        }
    }
}

// ---------------- fused per-(window,head) attention ----------------
// smem floats: 3*98*33 + 98*98 + 507 = 19813  (79252 bytes)
#define ATTN_SMEM_FLOATS (3 * NTOK * QST + NTOK * NTOK + TBL)

__global__ __launch_bounds__(256, 2) void attn_kernel() {
    extern __shared__ float sm[];
    float* sq  = sm;
    float* sk  = sq + NTOK * QST;
    float* sv  = sk + NTOK * QST;
    float* sS  = sv + NTOK * QST;          // 98*98
    float* sbt = sS + NTOK * NTOK;         // 507
    int bx = blockIdx.x;
    int w = bx >> 3, h = bx & 7;
    int tid = threadIdx.x;

    const float* base = g_qkv + (size_t)w * NTOK * 768 + h * HD;
    for (int e = tid; e < NTOK * HD; e += 256) {
        int n = e >> 5, d = e & 31;
        const float* r = base + (size_t)n * 768;
        sq[n * QST + d] = r[d];
        sk[n * QST + d] = r[256 + d];
        sv[n * QST + d] = r[512 + d];
    }
    for (int e = tid; e < TBL; e += 256) sbt[e] = g_bt[e * NH + h];
    __syncthreads();

    // L2-normalize rows; fold cosine scale into q
    float scale = g_scale[h];
    if (tid < NTOK) {
        float nq = 0.f, nk = 0.f;
        for (int d = 0; d < HD; d++) {
            float a = sq[tid * QST + d]; nq += a * a;
            float b = sk[tid * QST + d]; nk += b * b;
        }
        float iq = scale / fmaxf(sqrtf(nq), 1e-12f);
        float ik = 1.f   / fmaxf(sqrtf(nk), 1e-12f);
        for (int d = 0; d < HD; d++) {
            sq[tid * QST + d] *= iq;
            sk[tid * QST + d] *= ik;
        }
    }
    __syncthreads();

    // S = q @ k^T + rpb  (7x7 register tile, 196 active threads)
    if (tid < 196) {
        int ti = tid / 14, tj = tid % 14;
        float acc[7][7] = {};
        const float* qp = &sq[ti * 7 * QST];
        const float* kp = &sk[tj * 7 * QST];
        for (int d = 0; d < HD; d++) {
            float a[7], b[7];
            #pragma unroll
            for (int i = 0; i < 7; i++) a[i] = qp[i * QST + d];
            #pragma unroll
            for (int j = 0; j < 7; j++) b[j] = kp[j * QST + d];
            #pragma unroll
            for (int i = 0; i < 7; i++)
                #pragma unroll
                for (int j = 0; j < 7; j++) acc[i][j] += a[i] * b[j];
        }
        #pragma unroll
        for (int i = 0; i < 7; i++) {
            int gi = ti * 7 + i;
            int di = gi / 49, ri = gi % 49, hi = ri / 7, wi = ri % 7;
            #pragma unroll
            for (int j = 0; j < 7; j++) {
                int gj = tj * 7 + j;
                int dj = gj / 49, rj = gj % 49, hj = rj / 7, wj = rj % 7;
                int idx = (di - dj + 1) * 169 + (hi - hj + 6) * 13 + (wi - wj + 6);
                sS[gi * NTOK + gj] = acc[i][j] + sbt[idx];
            }
        }
    }
    __syncthreads();

    // row softmax (max-subtracted; logits can reach ~116)
    if (tid < NTOK) {
        float* row = &sS[tid * NTOK];
        float m = -1e30f;
        for (int j = 0; j < NTOK; j++) m = fmaxf(m, row[j]);
        float s = 0.f;
        for (int j = 0; j < NTOK; j++) { float e = __expf(row[j] - m); row[j] = e; s += e; }
        float inv = 1.f / s;
        for (int j = 0; j < NTOK; j++) row[j] *= inv;
    }
    __syncthreads();

    // O = P @ V  (7x4 register tile, 112 active threads), write [b,n,h*32+d]
    if (tid < 112) {
        int ti = tid / 8, tc = tid % 8;
        float acc[7][4] = {};
        for (int j = 0; j < NTOK; j++) {
            float p[7], vv[4];
            #pragma unroll
            for (int i = 0; i < 7; i++) p[i] = sS[(ti * 7 + i) * NTOK + j];
            #pragma unroll
            for (int c = 0; c < 4; c++) vv[c] = sv[j * QST + tc * 4 + c];
            #pragma unroll
            for (int i = 0; i < 7; i++)
                #pragma unroll
                for (int c = 0; c < 4; c++) acc[i][c] += p[i] * vv[c];
        }
        float* outb = g_att + (size_t)w * NTOK * DIM + h * HD + tc * 4;
        #pragma unroll
        for (int i = 0; i < 7; i++)
            #pragma unroll
            for (int c = 0; c < 4; c++)
                outb[(size_t)(ti * 7 + i) * DIM + c] = acc[i][c];
    }
}

// ---------------- launch ----------------
extern "C" void kernel_launch(void* const* d_in, const int* in_sizes, int n_in,
                              void* d_out, int out_size) {
    const float* x      = (const float*)d_in[0];
    const float* qkv_w  = (const float*)d_in[1];
    const float* q_bias = (const float*)d_in[2];
    const float* v_bias = (const float*)d_in[3];
    const float* ls     = (const float*)d_in[4];
    const float* cpb_w1 = (const float*)d_in[5];
    const float* cpb_b1 = (const float*)d_in[6];
    const float* cpb_w2 = (const float*)d_in[7];
    const float* proj_w = (const float*)d_in[8];
    const float* proj_b = (const float*)d_in[9];
    float* out = (float*)d_out;

    float *qkv, *att, *qkvwT, *projwT, *bias768;
    cudaGetSymbolAddress((void**)&qkv,     g_qkv);
    cudaGetSymbolAddress((void**)&att,     g_att);
    cudaGetSymbolAddress((void**)&qkvwT,   g_qkvwT);
    cudaGetSymbolAddress((void**)&projwT,  g_projwT);
    cudaGetSymbolAddress((void**)&bias768, g_bias768);

    setup_small<<<1, 768>>>(q_bias, v_bias, ls);
    transpose_k<<<(768 * 256 + 255) / 256, 256>>>(qkv_w, qkvwT, 768, 256);
    transpose_k<<<(256 * 256 + 255) / 256, 256>>>(proj_w, projwT, 256, 256);
    cpb_kernel<<<TBL, 512>>>(cpb_w1, cpb_b1, cpb_w2);

    // QKV: [200704,256] @ [256,768] + bias768
    gemm_tf32<<<dim3(3 * DIM / 128, M_TOT / 128), 256>>>(x, qkvwT, bias768, qkv, 3 * DIM);

    int smem_bytes = ATTN_SMEM_FLOATS * (int)sizeof(float);
    cudaFuncSetAttribute(attn_kernel, cudaFuncAttributeMaxDynamicSharedMemorySize, smem_bytes);
    attn_kernel<<<BW * NH, 256, smem_bytes>>>();

    // proj: [200704,256] @ [256,256] + proj_b
    gemm_tf32<<<dim3(DIM / 128, M_TOT / 128), 256>>>(att, projwT, proj_b, out, DIM);
}

// round 9
// speedup vs baseline: 1.8141x; 1.0407x over previous
#include <cuda_runtime.h>
#include <math.h>
#include <stdint.h>

#define DIM   256
#define NH    8
#define HD    32
#define NTOK  98
#define BW    2048
#define TBL   507                 // (2*2-1)*(2*7-1)*(2*7-1)
#define M_TOT (BW*NTOK)           // 200704
#define QST   33                  // padded smem row stride for q/k/v

// ---------------- device scratch (no allocations allowed) ----------------
__device__ float g_qkv[(size_t)BW * NTOK * 3 * DIM];   // 616 MB
__device__ float g_att[(size_t)BW * NTOK * DIM];       // 205 MB
__device__ float g_bt[TBL * NH];                       // 16*sigmoid(cpb) table
__device__ float g_bias768[3 * DIM];
__device__ float g_scale[NH];

// ---------------- setup: fused bias + per-head logit scale ----------------
__global__ void setup_small(const float* __restrict__ qb,
                            const float* __restrict__ vb,
                            const float* __restrict__ ls) {
    int t = threadIdx.x;                       // 768 threads
    float b;
    if (t < 256)       b = qb[t];
    else if (t < 512)  b = 0.f;
    else               b = vb[t - 512];
    g_bias768[t] = b;
    if (t < NH) g_scale[t] = expf(fminf(ls[t], 4.6051701860f)); // log(100)
}

// ---------------- CPB MLP: table -> relu -> w2 -> 16*sigmoid ----------------
__global__ void cpb_kernel(const float* __restrict__ w1, const float* __restrict__ b1,
                           const float* __restrict__ w2) {
    __shared__ float hid[512];
    int t = blockIdx.x;                        // 0..506
    int a = t / 169, rem = t % 169, b = rem / 13, c = rem % 13;
    const float eps = 1e-6f;
    float ga = (float)(a - 1) / (2.f - (1.f - eps)) * 8.f;
    float gb = (float)(b - 6) / (7.f - (1.f - eps)) * 8.f;
    float gc = (float)(c - 6) / (7.f - (1.f - eps)) * 8.f;
    const float il8 = 1.f / log2f(8.f);
    ga = copysignf(log2f(fabsf(ga) + 1.f) * il8, ga);
    gb = copysignf(log2f(fabsf(gb) + 1.f) * il8, gb);
    gc = copysignf(log2f(fabsf(gc) + 1.f) * il8, gc);
    int j = threadIdx.x;                       // 512 threads
    float hv = ga * w1[j * 3 + 0] + gb * w1[j * 3 + 1] + gc * w1[j * 3 + 2] + b1[j];
    hid[j] = fmaxf(hv, 0.f);
    __syncthreads();
    if (j < NH) {
        float acc = 0.f;
        for (int q = 0; q < 512; q++) acc += hid[q] * w2[j * 512 + q];
        g_bt[t * NH + j] = 16.f / (1.f + expf(-acc));
    }
}

// ---------------- tf32 helpers ----------------
__device__ __forceinline__ uint32_t f2tf(float x) {
    uint32_t u;
    asm("cvt.rna.tf32.f32 %0, %1;" : "=r"(u) : "f"(x));
    return u;
}

__device__ __forceinline__ uint32_t smem_u32(const void* p) {
    uint32_t a;
    asm("{ .reg .u64 t; cvta.to.shared.u64 t, %1; cvt.u32.u64 %0, t; }"
        : "=r"(a) : "l"(p));
    return a;
}

__device__ __forceinline__ void mma_tf32(float* d, const uint32_t* a,
                                         const uint32_t* b, const float* c) {
    asm volatile(
        "mma.sync.aligned.m16n8k8.row.col.f32.tf32.tf32.f32 "
        "{%0,%1,%2,%3}, {%4,%5,%6,%7}, {%8,%9}, {%10,%11,%12,%13};\n"
        : "=f"(d[0]), "=f"(d[1]), "=f"(d[2]), "=f"(d[3])
        : "r"(a[0]), "r"(a[1]), "r"(a[2]), "r"(a[3]),
          "r"(b[0]), "r"(b[1]),
          "f"(c[0]), "f"(c[1]), "f"(c[2]), "f"(c[3]));
}

#define CP16(dst, src) \
    asm volatile("cp.async.cg.shared.global [%0], [%1], 16;" :: "r"(dst), "l"(src))
#define CP_COMMIT() asm volatile("cp.async.commit_group;" ::: "memory")
#define CP_WAIT1()  asm volatile("cp.async.wait_group 1;" ::: "memory")
#define CP_WAIT0()  asm volatile("cp.async.wait_group 0;" ::: "memory")

// ---------------- tf32 mma.sync GEMM, cp.async 3-stage ----------------
// C[M,Nout] = A[M,256] @ W[Nout,256]^T + bias.  Both A and W are K-major.
// CTA tile 128x128, K-chunk 32, 3 smem stages of (A:128x36f, B:128x36f).
// PTX ISA m16n8k8 tf32 fragments (g = lane>>2, tg = lane&3):
//   A: a0=(g,tg) a1=(g+8,tg) a2=(g,tg+4) a3=(g+8,tg+4)
//   B(col): b0=(n=g,k=tg) b1=(n=g,k=tg+4)
//   C: c0,c1=(g, 2tg..2tg+1)  c2,c3=(g+8, 2tg..2tg+1)
#define KCH    32
#define NCHUNK 8
#define RST    36                           // smem row stride (floats)
#define STG    (128 * RST)                  // one matrix stage (floats)
#define GEMM_SMEM (3 * 2 * STG * 4)         // 110592 bytes

__global__ __launch_bounds__(256) void gemm_tc(const float* __restrict__ A,
                                               const float* __restrict__ W,
                                               const float* __restrict__ bias,
                                               float* __restrict__ C, int Nout) {
    extern __shared__ float sm[];
    uint32_t sbase = smem_u32(sm);
    int tid = threadIdx.x;
    int wid = tid >> 5, lane = tid & 31;
    int g = lane >> 2, tg = lane & 3;
    int m0 = blockIdx.y * 128, n0 = blockIdx.x * 128;
    int wm = (wid & 3) * 32, wn = (wid >> 2) * 64;

    float acc[2][8][4] = {};

    // staging: thread covers 4 x 16B per matrix per chunk
    int row0 = tid >> 3, seg = tid & 7;     // rows row0+32j, 16B segment
    const float* Ap = A + (size_t)(m0 + row0) * 256 + seg * 4;
    const float* Wp = W + (size_t)(n0 + row0) * 256 + seg * 4;

    #define STAGE_CHUNK(cc) do {                                                  \
        int _st = (cc) % 3;                                                       \
        uint32_t _ab = sbase + (uint32_t)(_st * 2 * STG) * 4;                     \
        uint32_t _bb = _ab + (uint32_t)STG * 4;                                   \
        _Pragma("unroll")                                                         \
        for (int _j = 0; _j < 4; _j++) {                                          \
            int _r = row0 + _j * 32;                                              \
            uint32_t _o = (uint32_t)(_r * RST + seg * 4) * 4;                     \
            CP16(_ab + _o, Ap + (size_t)_j * 32 * 256 + (cc) * KCH);              \
            CP16(_bb + _o, Wp + (size_t)_j * 32 * 256 + (cc) * KCH);              \
        }                                                                         \
        CP_COMMIT();                                                              \
    } while (0)

    STAGE_CHUNK(0);
    STAGE_CHUNK(1);

    for (int c = 0; c < NCHUNK; c++) {
        if (c == NCHUNK - 1) CP_WAIT0(); else CP_WAIT1();
        __syncthreads();
        if (c + 2 < NCHUNK) STAGE_CHUNK(c + 2);

        const float* As = sm + (c % 3) * 2 * STG;
        const float* Bs = As + STG;
        #pragma unroll
        for (int kk = 0; kk < KCH; kk += 8) {
            uint32_t af[2][4];
            #pragma unroll
            for (int mi = 0; mi < 2; mi++) {
                int r = wm + mi * 16 + g;
                af[mi][0] = f2tf(As[r * RST + kk + tg]);
                af[mi][1] = f2tf(As[(r + 8) * RST + kk + tg]);
                af[mi][2] = f2tf(As[r * RST + kk + tg + 4]);
                af[mi][3] = f2tf(As[(r + 8) * RST + kk + tg + 4]);
            }
            uint32_t bf[8][2];
            #pragma unroll
            for (int ni = 0; ni < 8; ni++) {
                int n = wn + ni * 8 + g;
                bf[ni][0] = f2tf(Bs[n * RST + kk + tg]);
                bf[ni][1] = f2tf(Bs[n * RST + kk + tg + 4]);
            }
            #pragma unroll
            for (int mi = 0; mi < 2; mi++)
                #pragma unroll
                for (int ni = 0; ni < 8; ni++)
                    mma_tf32(acc[mi][ni], af[mi], bf[ni], acc[mi][ni]);
        }
        __syncthreads();
    }

    // epilogue: add bias, write
    #pragma unroll
    for (int mi = 0; mi < 2; mi++) {
        #pragma unroll
        for (int ni = 0; ni < 8; ni++) {
            int row = m0 + wm + mi * 16 + g;
            int col = n0 + wn + ni * 8 + 2 * tg;
            float b0v = bias[col], b1v = bias[col + 1];
            *(float2*)&C[(size_t)row * Nout + col] =
                make_float2(acc[mi][ni][0] + b0v, acc[mi][ni][1] + b1v);
            *(float2*)&C[(size_t)(row + 8) * Nout + col] =
                make_float2(acc[mi][ni][2] + b0v, acc[mi][ni][3] + b1v);
        }
    }
}

// ---------------- fused per-(window,head) attention ----------------
// smem floats: 3*98*33 + 98*98 + 507 = 19813  (79252 bytes)
#define ATTN_SMEM_FLOATS (3 * NTOK * QST + NTOK * NTOK + TBL)

__global__ __launch_bounds__(256, 2) void attn_kernel() {
    extern __shared__ float sm[];
    float* sq  = sm;
    float* sk  = sq + NTOK * QST;
    float* sv  = sk + NTOK * QST;
    float* sS  = sv + NTOK * QST;          // 98*98
    float* sbt = sS + NTOK * NTOK;         // 507
    int bx = blockIdx.x;
    int w = bx >> 3, h = bx & 7;
    int tid = threadIdx.x;
    int warp = tid >> 5, lane = tid & 31;

    // float4 gmem loads, scalar smem stores (QST=33 is not 16B-aligned)
    const float* base = g_qkv + (size_t)w * NTOK * 768 + h * HD;
    for (int e = tid; e < NTOK * (HD / 4); e += 256) {
        int n = e >> 3, d4 = (e & 7) * 4;
        const float* r = base + (size_t)n * 768;
        float4 vq = *(const float4*)(r + d4);
        float4 vk = *(const float4*)(r + 256 + d4);
        float4 vv = *(const float4*)(r + 512 + d4);
        float* q = &sq[n * QST + d4];
        q[0] = vq.x; q[1] = vq.y; q[2] = vq.z; q[3] = vq.w;
        float* k = &sk[n * QST + d4];
        k[0] = vk.x; k[1] = vk.y; k[2] = vk.z; k[3] = vk.w;
        float* v = &sv[n * QST + d4];
        v[0] = vv.x; v[1] = vv.y; v[2] = vv.z; v[3] = vv.w;
    }
    for (int e = tid; e < TBL; e += 256) sbt[e] = g_bt[e * NH + h];
    __syncthreads();

    // L2-normalize rows; fold cosine scale into q
    float scale = g_scale[h];
    if (tid < NTOK) {
        float nq = 0.f, nk = 0.f;
        for (int d = 0; d < HD; d++) {
            float a = sq[tid * QST + d]; nq += a * a;
            float b = sk[tid * QST + d]; nk += b * b;
        }
        float iq = scale / fmaxf(sqrtf(nq), 1e-12f);
        float ik = 1.f   / fmaxf(sqrtf(nk), 1e-12f);
        for (int d = 0; d < HD; d++) {
            sq[tid * QST + d] *= iq;
            sk[tid * QST + d] *= ik;
        }
    }
    __syncthreads();

    // S = q @ k^T + rpb  (7x7 register tile, 196 active threads)
    if (tid < 196) {
        int ti = tid / 14, tj = tid % 14;
        float acc[7][7] = {};
        const float* qp = &sq[ti * 7 * QST];
        const float* kp = &sk[tj * 7 * QST];
        for (int d = 0; d < HD; d++) {
            float a[7], b[7];
            #pragma unroll
            for (int i = 0; i < 7; i++) a[i] = qp[i * QST + d];
            #pragma unroll
            for (int j = 0; j < 7; j++) b[j] = kp[j * QST + d];
            #pragma unroll
            for (int i = 0; i < 7; i++)
                #pragma unroll
                for (int j = 0; j < 7; j++) acc[i][j] += a[i] * b[j];
        }
        #pragma unroll
        for (int i = 0; i < 7; i++) {
            int gi = ti * 7 + i;
            int di = gi / 49, ri = gi % 49, hi = ri / 7, wi = ri % 7;
            #pragma unroll
            for (int j = 0; j < 7; j++) {
                int gj = tj * 7 + j;
                int dj = gj / 49, rj = gj % 49, hj = rj / 7, wj = rj % 7;
                int idx = (di - dj + 1) * 169 + (hi - hj + 6) * 13 + (wi - wj + 6);
                sS[gi * NTOK + gj] = acc[i][j] + sbt[idx];
            }
        }
    }
    __syncthreads();

    // warp-parallel row softmax (8 warps sweep 98 rows)
    for (int r = warp; r < NTOK; r += 8) {
        float* row = &sS[r * NTOK];
        float m = -1e30f;
        for (int j = lane; j < NTOK; j += 32) m = fmaxf(m, row[j]);
        #pragma unroll
        for (int o = 16; o; o >>= 1) m = fmaxf(m, __shfl_xor_sync(~0u, m, o));
        float s = 0.f;
        for (int j = lane; j < NTOK; j += 32) {
            float e = __expf(row[j] - m); row[j] = e; s += e;
        }
        #pragma unroll
        for (int o = 16; o; o >>= 1) s += __shfl_xor_sync(~0u, s, o);
        float inv = 1.f / s;
        for (int j = lane; j < NTOK; j += 32) row[j] *= inv;
    }
    __syncthreads();

    // O = P @ V  (7x2 register tile, 224 active threads), write [b,n,h*32+d]
    if (tid < 224) {
        int ti = tid >> 4, tc = tid & 15;
        float acc[7][2] = {};
        for (int j = 0; j < NTOK; j++) {
            float p[7];
            float v0 = sv[j * QST + tc * 2], v1 = sv[j * QST + tc * 2 + 1];
            #pragma unroll
            for (int i = 0; i < 7; i++) p[i] = sS[(ti * 7 + i) * NTOK + j];
            #pragma unroll
            for (int i = 0; i < 7; i++) {
                acc[i][0] += p[i] * v0;
                acc[i][1] += p[i] * v1;
            }
        }
        float* outb = g_att + (size_t)w * NTOK * DIM + h * HD + tc * 2;
        #pragma unroll
        for (int i = 0; i < 7; i++)
            *(float2*)&outb[(size_t)(ti * 7 + i) * DIM] = make_float2(acc[i][0], acc[i][1]);
    }
}

// ---------------- launch ----------------
extern "C" void kernel_launch(void* const* d_in, const int* in_sizes, int n_in,
                              void* d_out, int out_size) {
    const float* x      = (const float*)d_in[0];
    const float* qkv_w  = (const float*)d_in[1];
    const float* q_bias = (const float*)d_in[2];
    const float* v_bias = (const float*)d_in[3];
    const float* ls     = (const float*)d_in[4];
    const float* cpb_w1 = (const float*)d_in[5];
    const float* cpb_b1 = (const float*)d_in[6];
    const float* cpb_w2 = (const float*)d_in[7];
    const float* proj_w = (const float*)d_in[8];
    const float* proj_b = (const float*)d_in[9];
    float* out = (float*)d_out;

    float *qkv, *att, *bias768;
    cudaGetSymbolAddress((void**)&qkv,     g_qkv);
    cudaGetSymbolAddress((void**)&att,     g_att);
    cudaGetSymbolAddress((void**)&bias768, g_bias768);

    setup_small<<<1, 768>>>(q_bias, v_bias, ls);
    cpb_kernel<<<TBL, 512>>>(cpb_w1, cpb_b1, cpb_w2);

    cudaFuncSetAttribute(gemm_tc, cudaFuncAttributeMaxDynamicSharedMemorySize, GEMM_SMEM);

    // QKV: [200704,256] @ qkv_w[768,256]^T + bias768  (W consumed as native [N,K])
    gemm_tc<<<dim3(768 / 128, M_TOT / 128), 256, GEMM_SMEM>>>(x, qkv_w, bias768, qkv, 768);

    int smem_bytes = ATTN_SMEM_FLOATS * (int)sizeof(float);
    cudaFuncSetAttribute(attn_kernel, cudaFuncAttributeMaxDynamicSharedMemorySize, smem_bytes);
    attn_kernel<<<BW * NH, 256, smem_bytes>>>();

    // proj: [200704,256] @ proj_w[256,256]^T + proj_b
    gemm_tc<<<dim3(256 / 128, M_TOT / 128), 256, GEMM_SMEM>>>(att, proj_w, proj_b, out, 256);
}